// round 12
// baseline (speedup 1.0000x reference)
#include <cuda_runtime.h>
#include <cstdint>

#define D        256
#define NCODES   1024
#define BM       128
#define BN       128
#define KC       32
#define AS_STRIDE 264
#define BS_STRIDE 36
#define BSZ      (128 * BS_STRIDE)
#define MAXROWS  65536
#define GATHER_BLOCKS 8192
#define SAFE     0.35f
#define RROWS    8

__device__ float  g_cnorm[NCODES];
__device__ int    g_argmin[MAXROWS];
__device__ int    g_candrow[MAXROWS];
__device__ int    g_cand2[MAXROWS];
__device__ int    g_cand3[MAXROWS];
__device__ int    g_fullrow[MAXROWS];
__device__ int    g_ncand;
__device__ int    g_nfull;
__device__ double g_partial[GATHER_BLOCKS];

// ---------------------------------------------------------------------------
__device__ __forceinline__ uint32_t tf32r(float v) {
    uint32_t r;
    asm("cvt.rna.tf32.f32 %0, %1;" : "=r"(r) : "f"(v));
    return r;
}
__device__ __forceinline__ void mma8(float* d, const uint32_t* a,
                                     const uint32_t* b) {
    asm volatile(
        "mma.sync.aligned.m16n8k8.row.col.f32.tf32.tf32.f32 "
        "{%0,%1,%2,%3}, {%4,%5,%6,%7}, {%8,%9}, {%0,%1,%2,%3};"
        : "+f"(d[0]), "+f"(d[1]), "+f"(d[2]), "+f"(d[3])
        : "r"(a[0]), "r"(a[1]), "r"(a[2]), "r"(a[3]), "r"(b[0]), "r"(b[1]));
}
// insert (s,c) into 4-slot lexicographically sorted top-4 list
__device__ __forceinline__ void ins4(float s, int c, float* S, int* I) {
    if (s < S[3] || (s == S[3] && c < I[3])) {
        if (s < S[2] || (s == S[2] && c < I[2])) {
            S[3] = S[2]; I[3] = I[2];
            if (s < S[1] || (s == S[1] && c < I[1])) {
                S[2] = S[1]; I[2] = I[1];
                if (s < S[0] || (s == S[0] && c < I[0])) {
                    S[1] = S[0]; I[1] = I[0]; S[0] = s; I[0] = c;
                } else { S[1] = s; I[1] = c; }
            } else { S[2] = s; I[2] = c; }
        } else { S[3] = s; I[3] = c; }
    }
}

// ---------------------------------------------------------------------------
// Kernel 1: codebook norms (exact fp32) + reset counters
// ---------------------------------------------------------------------------
__global__ void norms_kernel(const float* __restrict__ cb) {
    int k = blockIdx.x;
    int lane = threadIdx.x;
    if (k == 0 && lane == 0) { g_ncand = 0; g_nfull = 0; }
    const float4* row = reinterpret_cast<const float4*>(cb + (size_t)k * D);
    float s = 0.f;
#pragma unroll
    for (int i = 0; i < 2; i++) {
        float4 v = row[lane + 32 * i];
        s += v.x * v.x + v.y * v.y + v.z * v.z + v.w * v.w;
    }
#pragma unroll
    for (int off = 16; off > 0; off >>= 1)
        s += __shfl_xor_sync(0xffffffffu, s, off);
    if (lane == 0) g_cnorm[k] = s;
}

// ---------------------------------------------------------------------------
// Kernel 2 (pass A): single-pass tf32 GEMM with double-buffered B,
// per-row TOP-4 + 3-tier flagging (safe / <=3-candidate / full rescan).
// ---------------------------------------------------------------------------
extern __shared__ float dynsmem[];
#define SMEM_BYTES ((BM * AS_STRIDE + 2 * BSZ) * 4)

__global__ __launch_bounds__(256)
void argmin_kernel(const float* __restrict__ x, const float* __restrict__ cb) {
    float* As = dynsmem;                        // [128][264]
    float* Bs = dynsmem + BM * AS_STRIDE;       // 2 x [128][36]
    __shared__ float tS[BM][4][4];
    __shared__ int   tI[BM][4][4];

    int tid  = threadIdx.x;
    int wid  = tid >> 5;
    int lane = tid & 31;
    int g    = lane >> 2;
    int tig  = lane & 3;
    int wm   = wid & 1;
    int wn   = wid >> 1;
    int m0   = blockIdx.x * BM;

    const float4* x4  = reinterpret_cast<const float4*>(x);
    const float4* cb4 = reinterpret_cast<const float4*>(cb);

    // per-thread B-stage indices (4 float4 per thread per chunk)
    int br_ = 0, bc_ = 0;   // packed below per-it; recomputed inline

    // ---- stage full A row-block once, tf32-rounded ----
#pragma unroll
    for (int it = 0; it < 32; it++) {
        int i  = tid + it * 256;
        int r  = i >> 6;
        int c4 = i & 63;
        float4 v = x4[(size_t)(m0 + r) * 64 + c4];
        float* dst = As + r * AS_STRIDE + c4 * 4;
        dst[0] = __uint_as_float(tf32r(v.x));
        dst[1] = __uint_as_float(tf32r(v.y));
        dst[2] = __uint_as_float(tf32r(v.z));
        dst[3] = __uint_as_float(tf32r(v.w));
    }

    float S[4];
    int   I[4];
#pragma unroll
    for (int i = 0; i < 4; i++) { S[i] = 3.4e38f; I[i] = 0x7fffffff; }
    // per-row state lives per (mi,h) pair -> 8 lists of 4 is too many regs;
    // keep one top-4 per owned row slot in local arrays:
    float Sr[8][4];
    int   Ir[8][4];
#pragma unroll
    for (int r = 0; r < 8; r++)
#pragma unroll
        for (int i = 0; i < 4; i++) { Sr[r][i] = 3.4e38f; Ir[r][i] = 0x7fffffff; }

    for (int nc = 0; nc < NCODES / BN; nc++) {
        float acc[4][4][4];
#pragma unroll
        for (int mi = 0; mi < 4; mi++)
#pragma unroll
            for (int ni = 0; ni < 4; ni++)
#pragma unroll
                for (int r = 0; r < 4; r++) acc[mi][ni][r] = 0.f;

        // ---- preload B chunk kc=0 into buffer 0 ----
        {
#pragma unroll
            for (int it = 0; it < 4; it++) {
                int i  = tid + it * 256;
                int r  = i >> 3;
                int c4 = i & 7;
                float4 v = cb4[(size_t)(nc * BN + r) * 64 + 0 * 8 + c4];
                float* dst = Bs + r * BS_STRIDE + c4 * 4;
                dst[0] = __uint_as_float(tf32r(v.x));
                dst[1] = __uint_as_float(tf32r(v.y));
                dst[2] = __uint_as_float(tf32r(v.z));
                dst[3] = __uint_as_float(tf32r(v.w));
            }
        }
        __syncthreads();

        for (int kc = 0; kc < D / KC; kc++) {
            // ---- prefetch next B chunk into registers ----
            float4 pf[4];
            if (kc < D / KC - 1) {
#pragma unroll
                for (int it = 0; it < 4; it++) {
                    int i  = tid + it * 256;
                    int r  = i >> 3;
                    int c4 = i & 7;
                    pf[it] = cb4[(size_t)(nc * BN + r) * 64 + (kc + 1) * 8 + c4];
                }
            }
            const float* Bc = Bs + (kc & 1) * BSZ;

#pragma unroll
            for (int ks = 0; ks < 4; ks++) {
                int kk = kc * KC + ks * 8;
                uint32_t af[4][4];
#pragma unroll
                for (int mi = 0; mi < 4; mi++) {
                    int ar = wm * 64 + mi * 16;
                    af[mi][0] = __float_as_uint(As[(ar + g)     * AS_STRIDE + kk + tig]);
                    af[mi][1] = __float_as_uint(As[(ar + g + 8) * AS_STRIDE + kk + tig]);
                    af[mi][2] = __float_as_uint(As[(ar + g)     * AS_STRIDE + kk + tig + 4]);
                    af[mi][3] = __float_as_uint(As[(ar + g + 8) * AS_STRIDE + kk + tig + 4]);
                }
                uint32_t bf[4][2];
#pragma unroll
                for (int ni = 0; ni < 4; ni++) {
                    int br = wn * 32 + ni * 8;
                    bf[ni][0] = __float_as_uint(Bc[(br + g) * BS_STRIDE + ks * 8 + tig]);
                    bf[ni][1] = __float_as_uint(Bc[(br + g) * BS_STRIDE + ks * 8 + tig + 4]);
                }
#pragma unroll
                for (int mi = 0; mi < 4; mi++)
#pragma unroll
                    for (int ni = 0; ni < 4; ni++)
                        mma8(acc[mi][ni], af[mi], bf[ni]);
            }

            // ---- store prefetched chunk into alternate buffer ----
            if (kc < D / KC - 1) {
                float* Bn = Bs + ((kc + 1) & 1) * BSZ;
#pragma unroll
                for (int it = 0; it < 4; it++) {
                    int i  = tid + it * 256;
                    int r  = i >> 3;
                    int c4 = i & 7;
                    float* dst = Bn + r * BS_STRIDE + c4 * 4;
                    dst[0] = __uint_as_float(tf32r(pf[it].x));
                    dst[1] = __uint_as_float(tf32r(pf[it].y));
                    dst[2] = __uint_as_float(tf32r(pf[it].z));
                    dst[3] = __uint_as_float(tf32r(pf[it].w));
                }
                __syncthreads();
            }
        }
        __syncthreads();   // all warps done reading last buffer before next nc preload

        // ---- top-4 update per owned row slot ----
#pragma unroll
        for (int mi = 0; mi < 4; mi++)
#pragma unroll
            for (int h = 0; h < 2; h++) {
                int r = mi * 2 + h;
#pragma unroll
                for (int ni = 0; ni < 4; ni++)
#pragma unroll
                    for (int q = 0; q < 2; q++) {
                        int code = nc * BN + wn * 32 + ni * 8 + 2 * tig + q;
                        float s = g_cnorm[code] - 2.f * acc[mi][ni][h * 2 + q];
                        ins4(s, code, Sr[r], Ir[r]);
                    }
            }
    }

    // ---- merge across the quad (tig partners) ----
#pragma unroll
    for (int r = 0; r < 8; r++) {
#pragma unroll
        for (int t = 1; t < 4; t <<= 1) {
            float os[4];
            int   oi[4];
#pragma unroll
            for (int i = 0; i < 4; i++) {
                os[i] = __shfl_xor_sync(0xffffffffu, Sr[r][i], t);
                oi[i] = __shfl_xor_sync(0xffffffffu, Ir[r][i], t);
            }
#pragma unroll
            for (int i = 0; i < 4; i++) ins4(os[i], oi[i], Sr[r], Ir[r]);
        }
    }
    // ---- write per-N-warp top-4 to smem ----
    if (tig == 0) {
#pragma unroll
        for (int mi = 0; mi < 4; mi++)
#pragma unroll
            for (int h = 0; h < 2; h++) {
                int row = wm * 64 + mi * 16 + h * 8 + g;
                int r = mi * 2 + h;
#pragma unroll
                for (int i = 0; i < 4; i++) {
                    tS[row][wn][i] = Sr[r][i];
                    tI[row][wn][i] = Ir[r][i];
                }
            }
    }
    __syncthreads();
    // ---- final per-row merge + tiering ----
    if (tid < BM) {
        float F[4];
        int   FI[4];
#pragma unroll
        for (int i = 0; i < 4; i++) { F[i] = tS[tid][0][i]; FI[i] = tI[tid][0][i]; }
#pragma unroll
        for (int w = 1; w < 4; w++)
#pragma unroll
            for (int i = 0; i < 4; i++) ins4(tS[tid][w][i], tI[tid][w][i], F, FI);

        int row = m0 + tid;
        g_argmin[row] = FI[0];
        if (F[1] - F[0] < SAFE) {
            if (F[3] - F[0] < SAFE) {
                int p = atomicAdd(&g_nfull, 1);
                g_fullrow[p] = row;
            } else {
                int p = atomicAdd(&g_ncand, 1);
                g_candrow[p] = row;
                g_cand2[p] = FI[1];
                g_cand3[p] = (F[2] - F[0] < SAFE) ? FI[2] : -1;
            }
        }
    }
}

// ---------------------------------------------------------------------------
// Kernel 2b: exact fp32 compare among <=3 candidates (one warp per row)
// ---------------------------------------------------------------------------
__global__ __launch_bounds__(256)
void cand_kernel(const float* __restrict__ x, const float* __restrict__ cb) {
    int lane = threadIdx.x & 31;
    int gw   = (blockIdx.x * blockDim.x + threadIdx.x) >> 5;
    int nw   = (gridDim.x * blockDim.x) >> 5;
    int cnt  = g_ncand;

    const float4* x4  = reinterpret_cast<const float4*>(x);
    const float4* cb4 = reinterpret_cast<const float4*>(cb);

    for (int k = gw; k < cnt; k += nw) {
        int row = g_candrow[k];
        int a   = g_argmin[row];
        int b   = g_cand2[k];
        int c   = g_cand3[k];
        float d1 = 0.f, d2 = 0.f, d3 = 0.f;
#pragma unroll
        for (int t = 0; t < 2; t++) {
            int p = lane + 32 * t;
            float4 xv = x4[(size_t)row * 64 + p];
            float4 e1 = cb4[(size_t)a * 64 + p];
            float4 e2 = cb4[(size_t)b * 64 + p];
            d1 += xv.x * e1.x + xv.y * e1.y + xv.z * e1.z + xv.w * e1.w;
            d2 += xv.x * e2.x + xv.y * e2.y + xv.z * e2.z + xv.w * e2.w;
            if (c >= 0) {
                float4 e3 = cb4[(size_t)c * 64 + p];
                d3 += xv.x * e3.x + xv.y * e3.y + xv.z * e3.z + xv.w * e3.w;
            }
        }
#pragma unroll
        for (int off = 16; off > 0; off >>= 1) {
            d1 += __shfl_xor_sync(0xffffffffu, d1, off);
            d2 += __shfl_xor_sync(0xffffffffu, d2, off);
            d3 += __shfl_xor_sync(0xffffffffu, d3, off);
        }
        if (lane == 0) {
            float bs = g_cnorm[a] - 2.f * d1;
            int   bi = a;
            float s2 = g_cnorm[b] - 2.f * d2;
            if (s2 < bs || (s2 == bs && b < bi)) { bs = s2; bi = b; }
            if (c >= 0) {
                float s3 = g_cnorm[c] - 2.f * d3;
                if (s3 < bs || (s3 == bs && c < bi)) { bs = s3; bi = c; }
            }
            if (bi != a) g_argmin[row] = bi;
        }
    }
}

// ---------------------------------------------------------------------------
// Kernel 2c: exact fp32 full rescore, fine-grained 8-row tiles
// thread (tr=tid>>6, tc=tid&63) owns rows {2tr,2tr+1}, codes {j*256+4tc+q}
// ---------------------------------------------------------------------------
__global__ __launch_bounds__(256)
void rescore_kernel(const float* __restrict__ x, const float* __restrict__ cb) {
    __shared__ float xs[RROWS][260];
    __shared__ int   rowid[RROWS];
    __shared__ float wv[8][2];
    __shared__ int   wi_[8][2];

    int tid  = threadIdx.x;
    int lane = tid & 31;
    int warp = tid >> 5;
    int tr   = tid >> 6;
    int tc   = tid & 63;
    int cnt  = g_nfull;

    const float4* x4  = reinterpret_cast<const float4*>(x);
    const float4* cb4 = reinterpret_cast<const float4*>(cb);

    for (int base = blockIdx.x * RROWS; base < cnt; base += gridDim.x * RROWS) {
        if (tid < RROWS)
            rowid[tid] = (base + tid < cnt) ? g_fullrow[base + tid] : -1;
        __syncthreads();
        for (int i = tid; i < RROWS * 64; i += 256) {
            int r  = i >> 6;
            int c4 = i & 63;
            int row = rowid[r];
            if (row >= 0) {
                float4 v = x4[(size_t)row * 64 + c4];
                *reinterpret_cast<float4*>(&xs[r][c4 * 4]) = v;
            }
        }
        __syncthreads();

        float rb[2];
        int   ri_[2];
#pragma unroll
        for (int r = 0; r < 2; r++) { rb[r] = 3.4e38f; ri_[r] = 0; }

        for (int j = 0; j < 4; j++) {
            int c0 = j * 256 + tc * 4;
            float acc[2][4];
#pragma unroll
            for (int r = 0; r < 2; r++)
#pragma unroll
                for (int q = 0; q < 4; q++) acc[r][q] = 0.f;
#pragma unroll 8
            for (int d4 = 0; d4 < 64; d4++) {
                float4 e[4];
#pragma unroll
                for (int q = 0; q < 4; q++)
                    e[q] = cb4[(size_t)(c0 + q) * 64 + d4];
#pragma unroll
                for (int r = 0; r < 2; r++) {
                    float4 xv = *reinterpret_cast<const float4*>(
                        &xs[tr * 2 + r][d4 * 4]);
#pragma unroll
                    for (int q = 0; q < 4; q++)
                        acc[r][q] += xv.x * e[q].x + xv.y * e[q].y +
                                     xv.z * e[q].z + xv.w * e[q].w;
                }
            }
#pragma unroll
            for (int q = 0; q < 4; q++) {
                int code = c0 + q;
                float cn = g_cnorm[code];
#pragma unroll
                for (int r = 0; r < 2; r++) {
                    float s = cn - 2.f * acc[r][q];
                    if (s < rb[r] || (s == rb[r] && code < ri_[r])) {
                        rb[r] = s;
                        ri_[r] = code;
                    }
                }
            }
        }

#pragma unroll
        for (int r = 0; r < 2; r++) {
#pragma unroll
            for (int t = 1; t < 32; t <<= 1) {
                float os = __shfl_xor_sync(0xffffffffu, rb[r], t);
                int   oi = __shfl_xor_sync(0xffffffffu, ri_[r], t);
                if (os < rb[r] || (os == rb[r] && oi < ri_[r])) {
                    rb[r] = os;
                    ri_[r] = oi;
                }
            }
        }
        if (lane == 0)
#pragma unroll
            for (int r = 0; r < 2; r++) { wv[warp][r] = rb[r]; wi_[warp][r] = ri_[r]; }
        __syncthreads();
        if (tid < RROWS) {
            int trr = tid >> 1, rr = tid & 1;
            float a = wv[2 * trr][rr];
            int   ai = wi_[2 * trr][rr];
            float b = wv[2 * trr + 1][rr];
            int   bi = wi_[2 * trr + 1][rr];
            if (b < a || (b == a && bi < ai)) { a = b; ai = bi; }
            int row = rowid[tid];
            if (row >= 0) g_argmin[row] = ai;
        }
        __syncthreads();
    }
}

// ---------------------------------------------------------------------------
// Kernel 3: gather + loss partials
// ---------------------------------------------------------------------------
__global__ __launch_bounds__(256)
void gather_kernel(const float* __restrict__ x, const float* __restrict__ cb,
                   float* __restrict__ out, int nrows) {
    __shared__ float warp_s[8];
    int lane = threadIdx.x & 31;
    int wip  = threadIdx.x >> 5;
    int row  = blockIdx.x * 8 + wip;

    float s = 0.f;
    if (row < nrows) {
        int idx = g_argmin[row];
        const float4* q4 = reinterpret_cast<const float4*>(cb + (size_t)idx * D);
        const float4* xr = reinterpret_cast<const float4*>(x + (size_t)row * D);
        float4* o4 = reinterpret_cast<float4*>(out) + (size_t)row * (D / 4);
#pragma unroll
        for (int t = 0; t < 2; t++) {
            int p = lane + 32 * t;
            float4 q  = q4[p];
            float4 xv = xr[p];
            o4[p] = q;
            float dx = q.x - xv.x, dy = q.y - xv.y;
            float dz = q.z - xv.z, dw = q.w - xv.w;
            s += dx * dx + dy * dy + dz * dz + dw * dw;
        }
    }
#pragma unroll
    for (int off = 16; off > 0; off >>= 1)
        s += __shfl_xor_sync(0xffffffffu, s, off);
    if (lane == 0) warp_s[wip] = s;
    __syncthreads();
    if (threadIdx.x == 0) {
        double tot = 0.0;
#pragma unroll
        for (int w = 0; w < 8; w++) tot += (double)warp_s[w];
        g_partial[blockIdx.x] = tot;
    }
}

// ---------------------------------------------------------------------------
// Kernel 4: final loss reduction
// ---------------------------------------------------------------------------
__global__ void loss_kernel(float* __restrict__ loss_out, int nblocks,
                            float inv_nd) {
    __shared__ double sh[256];
    double s = 0.0;
    for (int i = threadIdx.x; i < nblocks; i += 256) s += g_partial[i];
    sh[threadIdx.x] = s;
    __syncthreads();
    for (int off = 128; off > 0; off >>= 1) {
        if (threadIdx.x < off) sh[threadIdx.x] += sh[threadIdx.x + off];
        __syncthreads();
    }
    if (threadIdx.x == 0)
        *loss_out = (float)(1.25 * sh[0] * (double)inv_nd);
}

// ---------------------------------------------------------------------------
extern "C" void kernel_launch(void* const* d_in, const int* in_sizes, int n_in,
                              void* d_out, int out_size) {
    const float* x  = (const float*)d_in[0];
    const float* cb = (const float*)d_in[1];
    float* out = (float*)d_out;

    int n     = in_sizes[0];       // 16777216
    int nrows = n / D;             // 65536

    cudaFuncSetAttribute(argmin_kernel,
                         cudaFuncAttributeMaxDynamicSharedMemorySize,
                         SMEM_BYTES);

    norms_kernel<<<NCODES, 32>>>(cb);
    argmin_kernel<<<nrows / BM, 256, SMEM_BYTES>>>(x, cb);
    cand_kernel<<<128, 256>>>(x, cb);
    rescore_kernel<<<592, 256>>>(x, cb);

    int gblocks = (nrows + 7) / 8;      // 8192
    gather_kernel<<<gblocks, 256>>>(x, cb, out, nrows);
    loss_kernel<<<1, 256>>>(out + (out_size - 1), gblocks, 1.0f / (float)n);
}

// round 13
// speedup vs baseline: 1.3184x; 1.3184x over previous
#include <cuda_runtime.h>
#include <cstdint>

#define D        256
#define NCODES   1024
#define BM       128
#define BN       128
#define KC       32
#define AS_STRIDE 264
#define BS_STRIDE 36
#define MAXROWS  65536
#define GATHER_BLOCKS 8192
#define SAFE     0.35f
#define RROWS    8

__device__ float  g_cnorm[NCODES];
__device__ int    g_argmin[MAXROWS];
__device__ int    g_pairrow[MAXROWS];
__device__ int    g_pairi2[MAXROWS];
__device__ int    g_fullrow[MAXROWS];
__device__ int    g_npair;
__device__ int    g_nfull;
__device__ double g_partial[GATHER_BLOCKS];

// ---------------------------------------------------------------------------
__device__ __forceinline__ uint32_t tf32r(float v) {
    uint32_t r;
    asm("cvt.rna.tf32.f32 %0, %1;" : "=r"(r) : "f"(v));
    return r;
}
__device__ __forceinline__ void mma8(float* d, const uint32_t* a,
                                     const uint32_t* b) {
    asm volatile(
        "mma.sync.aligned.m16n8k8.row.col.f32.tf32.tf32.f32 "
        "{%0,%1,%2,%3}, {%4,%5,%6,%7}, {%8,%9}, {%0,%1,%2,%3};"
        : "+f"(d[0]), "+f"(d[1]), "+f"(d[2]), "+f"(d[3])
        : "r"(a[0]), "r"(a[1]), "r"(a[2]), "r"(a[3]), "r"(b[0]), "r"(b[1]));
}
// lexicographic (score,index) top-3 merge: (a1..a3) <- merge(a, b)
__device__ __forceinline__ void merge3(float& a1, int& ai1, float& a2, int& ai2,
                                       float& a3, float b1, int bi1, float b2,
                                       int bi2, float b3) {
    if (b1 < a1 || (b1 == a1 && bi1 < ai1)) {
        if (b2 < a1 || (b2 == a1 && bi2 < ai1)) {
            a3 = fminf(b3, a1);
            a1 = b1; ai1 = bi1; a2 = b2; ai2 = bi2;
        } else {
            a3 = fminf(b2, a2);
            a2 = a1; ai2 = ai1; a1 = b1; ai1 = bi1;
        }
    } else {
        if (a2 < b1 || (a2 == b1 && ai2 < bi1)) {
            a3 = fminf(a3, b1);
        } else {
            a3 = fminf(a2, b2);
            a2 = b1; ai2 = bi1;
        }
    }
}

// ---------------------------------------------------------------------------
// Kernel 1: codebook norms (exact fp32) + reset counters
// ---------------------------------------------------------------------------
__global__ void norms_kernel(const float* __restrict__ cb) {
    int k = blockIdx.x;
    int lane = threadIdx.x;
    if (k == 0 && lane == 0) { g_npair = 0; g_nfull = 0; }
    const float4* row = reinterpret_cast<const float4*>(cb + (size_t)k * D);
    float s = 0.f;
#pragma unroll
    for (int i = 0; i < 2; i++) {
        float4 v = row[lane + 32 * i];
        s += v.x * v.x + v.y * v.y + v.z * v.z + v.w * v.w;
    }
#pragma unroll
    for (int off = 16; off > 0; off >>= 1)
        s += __shfl_xor_sync(0xffffffffu, s, off);
    if (lane == 0) g_cnorm[k] = s;
}

// ---------------------------------------------------------------------------
// Kernel 2 (pass A): single-pass tf32 GEMM, per-row TOP-3 + tiered flagging.
// (round-11 structure: single-buffered B, no prefetch, no spills)
// ---------------------------------------------------------------------------
extern __shared__ float dynsmem[];
#define SMEM_BYTES ((BM * AS_STRIDE + BN * BS_STRIDE) * 4)

__global__ __launch_bounds__(256)
void argmin_kernel(const float* __restrict__ x, const float* __restrict__ cb) {
    float* As = dynsmem;
    float* Bs = dynsmem + BM * AS_STRIDE;
    __shared__ float tv1[BM][4], tv2[BM][4], tv3[BM][4];
    __shared__ int   ti1[BM][4], ti2[BM][4];

    int tid  = threadIdx.x;
    int wid  = tid >> 5;
    int lane = tid & 31;
    int g    = lane >> 2;
    int tig  = lane & 3;
    int wm   = wid & 1;
    int wn   = wid >> 1;
    int m0   = blockIdx.x * BM;

    const float4* x4  = reinterpret_cast<const float4*>(x);
    const float4* cb4 = reinterpret_cast<const float4*>(cb);

#pragma unroll
    for (int it = 0; it < 32; it++) {
        int i  = tid + it * 256;
        int r  = i >> 6;
        int c4 = i & 63;
        float4 v = x4[(size_t)(m0 + r) * 64 + c4];
        float* dst = As + r * AS_STRIDE + c4 * 4;
        dst[0] = __uint_as_float(tf32r(v.x));
        dst[1] = __uint_as_float(tf32r(v.y));
        dst[2] = __uint_as_float(tf32r(v.z));
        dst[3] = __uint_as_float(tf32r(v.w));
    }

    float b1[8], b2[8], b3[8];
    int   i1[8], i2[8];
#pragma unroll
    for (int i = 0; i < 8; i++) {
        b1[i] = 3.4e38f; b2[i] = 3.4e38f; b3[i] = 3.4e38f;
        i1[i] = 0; i2[i] = 0;
    }

    for (int nc = 0; nc < NCODES / BN; nc++) {
        float acc[4][4][4];
#pragma unroll
        for (int mi = 0; mi < 4; mi++)
#pragma unroll
            for (int ni = 0; ni < 4; ni++)
#pragma unroll
                for (int r = 0; r < 4; r++) acc[mi][ni][r] = 0.f;

        for (int kc = 0; kc < D / KC; kc++) {
            __syncthreads();
#pragma unroll
            for (int it = 0; it < 4; it++) {
                int i  = tid + it * 256;
                int r  = i >> 3;
                int c4 = i & 7;
                float4 v = cb4[(size_t)(nc * BN + r) * 64 + kc * 8 + c4];
                float* dst = Bs + r * BS_STRIDE + c4 * 4;
                dst[0] = __uint_as_float(tf32r(v.x));
                dst[1] = __uint_as_float(tf32r(v.y));
                dst[2] = __uint_as_float(tf32r(v.z));
                dst[3] = __uint_as_float(tf32r(v.w));
            }
            __syncthreads();

#pragma unroll
            for (int ks = 0; ks < 4; ks++) {
                int kk = kc * KC + ks * 8;
                uint32_t af[4][4];
#pragma unroll
                for (int mi = 0; mi < 4; mi++) {
                    int ar = wm * 64 + mi * 16;
                    af[mi][0] = __float_as_uint(As[(ar + g)     * AS_STRIDE + kk + tig]);
                    af[mi][1] = __float_as_uint(As[(ar + g + 8) * AS_STRIDE + kk + tig]);
                    af[mi][2] = __float_as_uint(As[(ar + g)     * AS_STRIDE + kk + tig + 4]);
                    af[mi][3] = __float_as_uint(As[(ar + g + 8) * AS_STRIDE + kk + tig + 4]);
                }
                uint32_t bf[4][2];
#pragma unroll
                for (int ni = 0; ni < 4; ni++) {
                    int br = wn * 32 + ni * 8;
                    bf[ni][0] = __float_as_uint(Bs[(br + g) * BS_STRIDE + ks * 8 + tig]);
                    bf[ni][1] = __float_as_uint(Bs[(br + g) * BS_STRIDE + ks * 8 + tig + 4]);
                }
#pragma unroll
                for (int mi = 0; mi < 4; mi++)
#pragma unroll
                    for (int ni = 0; ni < 4; ni++)
                        mma8(acc[mi][ni], af[mi], bf[ni]);
            }
        }

        // ---- top-3 update (codes ascending within thread) ----
#pragma unroll
        for (int mi = 0; mi < 4; mi++)
#pragma unroll
            for (int h = 0; h < 2; h++) {
                int r = mi * 2 + h;
#pragma unroll
                for (int ni = 0; ni < 4; ni++)
#pragma unroll
                    for (int q = 0; q < 2; q++) {
                        int code = nc * BN + wn * 32 + ni * 8 + 2 * tig + q;
                        float s = g_cnorm[code] - 2.f * acc[mi][ni][h * 2 + q];
                        if (s < b1[r]) {
                            b3[r] = b2[r]; b2[r] = b1[r]; i2[r] = i1[r];
                            b1[r] = s; i1[r] = code;
                        } else if (s < b2[r]) {
                            b3[r] = b2[r]; b2[r] = s; i2[r] = code;
                        } else if (s < b3[r]) {
                            b3[r] = s;
                        }
                    }
            }
    }

    // ---- merge across quad ----
#pragma unroll
    for (int i = 0; i < 8; i++) {
#pragma unroll
        for (int t = 1; t < 4; t <<= 1) {
            float ob1 = __shfl_xor_sync(0xffffffffu, b1[i], t);
            int   oi1 = __shfl_xor_sync(0xffffffffu, i1[i], t);
            float ob2 = __shfl_xor_sync(0xffffffffu, b2[i], t);
            int   oi2 = __shfl_xor_sync(0xffffffffu, i2[i], t);
            float ob3 = __shfl_xor_sync(0xffffffffu, b3[i], t);
            merge3(b1[i], i1[i], b2[i], i2[i], b3[i], ob1, oi1, ob2, oi2, ob3);
        }
    }
    // ---- merge across 4 N-warps ----
    if (tig == 0) {
#pragma unroll
        for (int mi = 0; mi < 4; mi++)
#pragma unroll
            for (int h = 0; h < 2; h++) {
                int row = wm * 64 + mi * 16 + h * 8 + g;
                int r = mi * 2 + h;
                tv1[row][wn] = b1[r]; ti1[row][wn] = i1[r];
                tv2[row][wn] = b2[r]; ti2[row][wn] = i2[r];
                tv3[row][wn] = b3[r];
            }
    }
    __syncthreads();
    if (tid < BM) {
        float f1 = tv1[tid][0], f2 = tv2[tid][0], f3 = tv3[tid][0];
        int   fi1 = ti1[tid][0], fi2 = ti2[tid][0];
#pragma unroll
        for (int w = 1; w < 4; w++)
            merge3(f1, fi1, f2, fi2, f3,
                   tv1[tid][w], ti1[tid][w], tv2[tid][w], ti2[tid][w],
                   tv3[tid][w]);
        int row = m0 + tid;
        g_argmin[row] = fi1;
        if (f2 - f1 < SAFE) {
            if (f3 - f1 < SAFE) {
                int p = atomicAdd(&g_nfull, 1);
                g_fullrow[p] = row;
            } else {
                int p = atomicAdd(&g_npair, 1);
                g_pairrow[p] = row;
                g_pairi2[p] = fi2;
            }
        }
    }
}

// ---------------------------------------------------------------------------
// Kernel 2b: exact fp32 pair compare (one warp per flagged pair-row)
// ---------------------------------------------------------------------------
__global__ __launch_bounds__(256)
void pair_kernel(const float* __restrict__ x, const float* __restrict__ cb) {
    int lane = threadIdx.x & 31;
    int gw   = (blockIdx.x * blockDim.x + threadIdx.x) >> 5;
    int nw   = (gridDim.x * blockDim.x) >> 5;
    int cnt  = g_npair;

    const float4* x4  = reinterpret_cast<const float4*>(x);
    const float4* cb4 = reinterpret_cast<const float4*>(cb);

    for (int k = gw; k < cnt; k += nw) {
        int row = g_pairrow[k];
        int a   = g_argmin[row];
        int b   = g_pairi2[k];
        float d1 = 0.f, d2 = 0.f;
#pragma unroll
        for (int t = 0; t < 2; t++) {
            int p = lane + 32 * t;
            float4 xv = x4[(size_t)row * 64 + p];
            float4 e1 = cb4[(size_t)a * 64 + p];
            float4 e2 = cb4[(size_t)b * 64 + p];
            d1 += xv.x * e1.x + xv.y * e1.y + xv.z * e1.z + xv.w * e1.w;
            d2 += xv.x * e2.x + xv.y * e2.y + xv.z * e2.z + xv.w * e2.w;
        }
#pragma unroll
        for (int off = 16; off > 0; off >>= 1) {
            d1 += __shfl_xor_sync(0xffffffffu, d1, off);
            d2 += __shfl_xor_sync(0xffffffffu, d2, off);
        }
        if (lane == 0) {
            float s1 = g_cnorm[a] - 2.f * d1;
            float s2 = g_cnorm[b] - 2.f * d2;
            if (s2 < s1 || (s2 == s1 && b < a)) g_argmin[row] = b;
        }
    }
}

// ---------------------------------------------------------------------------
// Kernel 2c: exact fp32 full rescore, fine-grained 8-row tiles
// thread (tr=tid>>6, tc=tid&63) owns rows {2tr,2tr+1}, codes {j*256+4tc+q}
// ---------------------------------------------------------------------------
__global__ __launch_bounds__(256)
void rescore_kernel(const float* __restrict__ x, const float* __restrict__ cb) {
    __shared__ float xs[RROWS][260];
    __shared__ int   rowid[RROWS];
    __shared__ float wv[8][2];
    __shared__ int   wi_[8][2];

    int tid  = threadIdx.x;
    int lane = tid & 31;
    int warp = tid >> 5;
    int tr   = tid >> 6;
    int tc   = tid & 63;
    int cnt  = g_nfull;

    const float4* x4  = reinterpret_cast<const float4*>(x);
    const float4* cb4 = reinterpret_cast<const float4*>(cb);

    for (int base = blockIdx.x * RROWS; base < cnt; base += gridDim.x * RROWS) {
        if (tid < RROWS)
            rowid[tid] = (base + tid < cnt) ? g_fullrow[base + tid] : -1;
        __syncthreads();
        for (int i = tid; i < RROWS * 64; i += 256) {
            int r  = i >> 6;
            int c4 = i & 63;
            int row = rowid[r];
            if (row >= 0) {
                float4 v = x4[(size_t)row * 64 + c4];
                *reinterpret_cast<float4*>(&xs[r][c4 * 4]) = v;
            }
        }
        __syncthreads();

        float rb[2];
        int   ri_[2];
#pragma unroll
        for (int r = 0; r < 2; r++) { rb[r] = 3.4e38f; ri_[r] = 0; }

        for (int j = 0; j < 4; j++) {
            int c0 = j * 256 + tc * 4;
            float acc[2][4];
#pragma unroll
            for (int r = 0; r < 2; r++)
#pragma unroll
                for (int q = 0; q < 4; q++) acc[r][q] = 0.f;
#pragma unroll 8
            for (int d4 = 0; d4 < 64; d4++) {
                float4 e[4];
#pragma unroll
                for (int q = 0; q < 4; q++)
                    e[q] = cb4[(size_t)(c0 + q) * 64 + d4];
#pragma unroll
                for (int r = 0; r < 2; r++) {
                    float4 xv = *reinterpret_cast<const float4*>(
                        &xs[tr * 2 + r][d4 * 4]);
#pragma unroll
                    for (int q = 0; q < 4; q++)
                        acc[r][q] += xv.x * e[q].x + xv.y * e[q].y +
                                     xv.z * e[q].z + xv.w * e[q].w;
                }
            }
#pragma unroll
            for (int q = 0; q < 4; q++) {
                int code = c0 + q;
                float cn = g_cnorm[code];
#pragma unroll
                for (int r = 0; r < 2; r++) {
                    float s = cn - 2.f * acc[r][q];
                    if (s < rb[r] || (s == rb[r] && code < ri_[r])) {
                        rb[r] = s;
                        ri_[r] = code;
                    }
                }
            }
        }

#pragma unroll
        for (int r = 0; r < 2; r++) {
#pragma unroll
            for (int t = 1; t < 32; t <<= 1) {
                float os = __shfl_xor_sync(0xffffffffu, rb[r], t);
                int   oi = __shfl_xor_sync(0xffffffffu, ri_[r], t);
                if (os < rb[r] || (os == rb[r] && oi < ri_[r])) {
                    rb[r] = os;
                    ri_[r] = oi;
                }
            }
        }
        if (lane == 0)
#pragma unroll
            for (int r = 0; r < 2; r++) { wv[warp][r] = rb[r]; wi_[warp][r] = ri_[r]; }
        __syncthreads();
        if (tid < RROWS) {
            int trr = tid >> 1, rr = tid & 1;
            float a = wv[2 * trr][rr];
            int   ai = wi_[2 * trr][rr];
            float b = wv[2 * trr + 1][rr];
            int   bi = wi_[2 * trr + 1][rr];
            if (b < a || (b == a && bi < ai)) { a = b; ai = bi; }
            int row = rowid[tid];
            if (row >= 0) g_argmin[row] = ai;
        }
        __syncthreads();
    }
}

// ---------------------------------------------------------------------------
// Kernel 3: gather + loss partials
// ---------------------------------------------------------------------------
__global__ __launch_bounds__(256)
void gather_kernel(const float* __restrict__ x, const float* __restrict__ cb,
                   float* __restrict__ out, int nrows) {
    __shared__ float warp_s[8];
    int lane = threadIdx.x & 31;
    int wip  = threadIdx.x >> 5;
    int row  = blockIdx.x * 8 + wip;

    float s = 0.f;
    if (row < nrows) {
        int idx = g_argmin[row];
        const float4* q4 = reinterpret_cast<const float4*>(cb + (size_t)idx * D);
        const float4* xr = reinterpret_cast<const float4*>(x + (size_t)row * D);
        float4* o4 = reinterpret_cast<float4*>(out) + (size_t)row * (D / 4);
#pragma unroll
        for (int t = 0; t < 2; t++) {
            int p = lane + 32 * t;
            float4 q  = q4[p];
            float4 xv = xr[p];
            o4[p] = q;
            float dx = q.x - xv.x, dy = q.y - xv.y;
            float dz = q.z - xv.z, dw = q.w - xv.w;
            s += dx * dx + dy * dy + dz * dz + dw * dw;
        }
    }
#pragma unroll
    for (int off = 16; off > 0; off >>= 1)
        s += __shfl_xor_sync(0xffffffffu, s, off);
    if (lane == 0) warp_s[wip] = s;
    __syncthreads();
    if (threadIdx.x == 0) {
        double tot = 0.0;
#pragma unroll
        for (int w = 0; w < 8; w++) tot += (double)warp_s[w];
        g_partial[blockIdx.x] = tot;
    }
}

// ---------------------------------------------------------------------------
// Kernel 4: final loss reduction
// ---------------------------------------------------------------------------
__global__ void loss_kernel(float* __restrict__ loss_out, int nblocks,
                            float inv_nd) {
    __shared__ double sh[256];
    double s = 0.0;
    for (int i = threadIdx.x; i < nblocks; i += 256) s += g_partial[i];
    sh[threadIdx.x] = s;
    __syncthreads();
    for (int off = 128; off > 0; off >>= 1) {
        if (threadIdx.x < off) sh[threadIdx.x] += sh[threadIdx.x + off];
        __syncthreads();
    }
    if (threadIdx.x == 0)
        *loss_out = (float)(1.25 * sh[0] * (double)inv_nd);
}

// ---------------------------------------------------------------------------
extern "C" void kernel_launch(void* const* d_in, const int* in_sizes, int n_in,
                              void* d_out, int out_size) {
    const float* x  = (const float*)d_in[0];
    const float* cb = (const float*)d_in[1];
    float* out = (float*)d_out;

    int n     = in_sizes[0];       // 16777216
    int nrows = n / D;             // 65536

    cudaFuncSetAttribute(argmin_kernel,
                         cudaFuncAttributeMaxDynamicSharedMemorySize,
                         SMEM_BYTES);

    norms_kernel<<<NCODES, 32>>>(cb);
    argmin_kernel<<<nrows / BM, 256, SMEM_BYTES>>>(x, cb);
    pair_kernel<<<128, 256>>>(x, cb);
    rescore_kernel<<<592, 256>>>(x, cb);

    int gblocks = (nrows + 7) / 8;      // 8192
    gather_kernel<<<gblocks, 256>>>(x, cb, out, nrows);
    loss_kernel<<<1, 256>>>(out + (out_size - 1), gblocks, 1.0f / (float)n);
}

// round 14
// speedup vs baseline: 1.4078x; 1.0678x over previous
#include <cuda_runtime.h>
#include <cstdint>

#define D        256
#define NCODES   1024
#define BM       128
#define BN       128
#define KC       32
#define AS_STRIDE 264
#define BS_STRIDE 36
#define MAXROWS  65536
#define GATHER_BLOCKS 8192
#define MARGIN   0.28f
#define RROWS    32

__device__ float  g_cnorm[NCODES];
__device__ int    g_argmin[MAXROWS];
__device__ int    g_flagged[MAXROWS];
__device__ int    g_flagcnt;
__device__ double g_partial[GATHER_BLOCKS];

// ---------------------------------------------------------------------------
__device__ __forceinline__ uint32_t tf32r(float v) {
    uint32_t r;
    asm("cvt.rna.tf32.f32 %0, %1;" : "=r"(r) : "f"(v));
    return r;
}
__device__ __forceinline__ void mma8(float* d, const uint32_t* a,
                                     const uint32_t* b) {
    asm volatile(
        "mma.sync.aligned.m16n8k8.row.col.f32.tf32.tf32.f32 "
        "{%0,%1,%2,%3}, {%4,%5,%6,%7}, {%8,%9}, {%0,%1,%2,%3};"
        : "+f"(d[0]), "+f"(d[1]), "+f"(d[2]), "+f"(d[3])
        : "r"(a[0]), "r"(a[1]), "r"(a[2]), "r"(a[3]), "r"(b[0]), "r"(b[1]));
}

// ---------------------------------------------------------------------------
// Kernel 1: codebook norms (exact fp32) + reset flag counter
// ---------------------------------------------------------------------------
__global__ void norms_kernel(const float* __restrict__ cb) {
    int k = blockIdx.x;
    int lane = threadIdx.x;
    if (k == 0 && lane == 0) g_flagcnt = 0;
    const float4* row = reinterpret_cast<const float4*>(cb + (size_t)k * D);
    float s = 0.f;
#pragma unroll
    for (int i = 0; i < 2; i++) {
        float4 v = row[lane + 32 * i];
        s += v.x * v.x + v.y * v.y + v.z * v.z + v.w * v.w;
    }
#pragma unroll
    for (int off = 16; off > 0; off >>= 1)
        s += __shfl_xor_sync(0xffffffffu, s, off);
    if (lane == 0) g_cnorm[k] = s;
}

// ---------------------------------------------------------------------------
// Kernel 2 (pass A): single-pass tf32 GEMM, per-row top-2 + argmin + flagging.
// (round-8 structure: lean top-2 tracking, mma-pipe-bound)
// ---------------------------------------------------------------------------
extern __shared__ float dynsmem[];
#define SMEM_BYTES ((BM * AS_STRIDE + BN * BS_STRIDE) * 4)

__global__ __launch_bounds__(256)
void argmin_kernel(const float* __restrict__ x, const float* __restrict__ cb) {
    float* As = dynsmem;                       // [128][264] tf32-rounded
    float* Bs = dynsmem + BM * AS_STRIDE;      // [128][36]  tf32-rounded
    __shared__ float tv1[BM][4];
    __shared__ float tv2[BM][4];
    __shared__ int   ti1[BM][4];

    int tid  = threadIdx.x;
    int wid  = tid >> 5;
    int lane = tid & 31;
    int g    = lane >> 2;
    int tig  = lane & 3;
    int wm   = wid & 1;
    int wn   = wid >> 1;
    int m0   = blockIdx.x * BM;

    const float4* x4  = reinterpret_cast<const float4*>(x);
    const float4* cb4 = reinterpret_cast<const float4*>(cb);

    // ---- stage full A row-block once, tf32-rounded ----
#pragma unroll
    for (int it = 0; it < 32; it++) {
        int i  = tid + it * 256;
        int r  = i >> 6;
        int c4 = i & 63;
        float4 v = x4[(size_t)(m0 + r) * 64 + c4];
        float* dst = As + r * AS_STRIDE + c4 * 4;
        dst[0] = __uint_as_float(tf32r(v.x));
        dst[1] = __uint_as_float(tf32r(v.y));
        dst[2] = __uint_as_float(tf32r(v.z));
        dst[3] = __uint_as_float(tf32r(v.w));
    }

    float b1[8], b2[8];
    int   i1[8];
#pragma unroll
    for (int i = 0; i < 8; i++) { b1[i] = 3.4e38f; b2[i] = 3.4e38f; i1[i] = 0; }

    for (int nc = 0; nc < NCODES / BN; nc++) {
        float acc[4][4][4];
#pragma unroll
        for (int mi = 0; mi < 4; mi++)
#pragma unroll
            for (int ni = 0; ni < 4; ni++)
#pragma unroll
                for (int r = 0; r < 4; r++) acc[mi][ni][r] = 0.f;

        for (int kc = 0; kc < D / KC; kc++) {
            __syncthreads();
#pragma unroll
            for (int it = 0; it < 4; it++) {
                int i  = tid + it * 256;
                int r  = i >> 3;
                int c4 = i & 7;
                float4 v = cb4[(size_t)(nc * BN + r) * 64 + kc * 8 + c4];
                float* dst = Bs + r * BS_STRIDE + c4 * 4;
                dst[0] = __uint_as_float(tf32r(v.x));
                dst[1] = __uint_as_float(tf32r(v.y));
                dst[2] = __uint_as_float(tf32r(v.z));
                dst[3] = __uint_as_float(tf32r(v.w));
            }
            __syncthreads();

#pragma unroll
            for (int ks = 0; ks < 4; ks++) {
                int kk = kc * KC + ks * 8;
                uint32_t af[4][4];
#pragma unroll
                for (int mi = 0; mi < 4; mi++) {
                    int ar = wm * 64 + mi * 16;
                    af[mi][0] = __float_as_uint(As[(ar + g)     * AS_STRIDE + kk + tig]);
                    af[mi][1] = __float_as_uint(As[(ar + g + 8) * AS_STRIDE + kk + tig]);
                    af[mi][2] = __float_as_uint(As[(ar + g)     * AS_STRIDE + kk + tig + 4]);
                    af[mi][3] = __float_as_uint(As[(ar + g + 8) * AS_STRIDE + kk + tig + 4]);
                }
                uint32_t bf[4][2];
#pragma unroll
                for (int ni = 0; ni < 4; ni++) {
                    int br = wn * 32 + ni * 8;
                    bf[ni][0] = __float_as_uint(Bs[(br + g) * BS_STRIDE + ks * 8 + tig]);
                    bf[ni][1] = __float_as_uint(Bs[(br + g) * BS_STRIDE + ks * 8 + tig + 4]);
                }
#pragma unroll
                for (int mi = 0; mi < 4; mi++)
#pragma unroll
                    for (int ni = 0; ni < 4; ni++)
                        mma8(acc[mi][ni], af[mi], bf[ni]);
            }
        }

        // ---- top-2 + argmin update ----
#pragma unroll
        for (int mi = 0; mi < 4; mi++)
#pragma unroll
            for (int h = 0; h < 2; h++) {
                int bi_ = mi * 2 + h;
#pragma unroll
                for (int ni = 0; ni < 4; ni++)
#pragma unroll
                    for (int q = 0; q < 2; q++) {
                        int code = nc * BN + wn * 32 + ni * 8 + 2 * tig + q;
                        float s = g_cnorm[code] - 2.f * acc[mi][ni][h * 2 + q];
                        if (s < b1[bi_] || (s == b1[bi_] && code < i1[bi_])) {
                            b2[bi_] = b1[bi_];
                            b1[bi_] = s;
                            i1[bi_] = code;
                        } else if (s < b2[bi_]) {
                            b2[bi_] = s;
                        }
                    }
            }
    }

    // ---- merge across quad (tig) ----
#pragma unroll
    for (int i = 0; i < 8; i++) {
#pragma unroll
        for (int t = 1; t < 4; t <<= 1) {
            float ob1 = __shfl_xor_sync(0xffffffffu, b1[i], t);
            int   oi1 = __shfl_xor_sync(0xffffffffu, i1[i], t);
            float ob2 = __shfl_xor_sync(0xffffffffu, b2[i], t);
            if (ob1 < b1[i] || (ob1 == b1[i] && oi1 < i1[i])) {
                b2[i] = fminf(b1[i], ob2);
                b1[i] = ob1;
                i1[i] = oi1;
            } else {
                b2[i] = fminf(b2[i], ob1);
            }
        }
    }
    // ---- merge across 4 N-warps ----
    if (tig == 0) {
#pragma unroll
        for (int mi = 0; mi < 4; mi++)
#pragma unroll
            for (int h = 0; h < 2; h++) {
                int row = wm * 64 + mi * 16 + h * 8 + g;
                tv1[row][wn] = b1[mi * 2 + h];
                tv2[row][wn] = b2[mi * 2 + h];
                ti1[row][wn] = i1[mi * 2 + h];
            }
    }
    __syncthreads();
    if (tid < BM) {
        float fb1 = tv1[tid][0], fb2 = tv2[tid][0];
        int   fi1 = ti1[tid][0];
#pragma unroll
        for (int w = 1; w < 4; w++) {
            float ob1 = tv1[tid][w], ob2 = tv2[tid][w];
            int   oi1 = ti1[tid][w];
            if (ob1 < fb1 || (ob1 == fb1 && oi1 < fi1)) {
                fb2 = fminf(fb1, ob2);
                fb1 = ob1;
                fi1 = oi1;
            } else {
                fb2 = fminf(fb2, ob1);
            }
        }
        g_argmin[m0 + tid] = fi1;
        if (fb2 - fb1 < MARGIN) {
            int p = atomicAdd(&g_flagcnt, 1);
            g_flagged[p] = m0 + tid;
        }
    }
}

// ---------------------------------------------------------------------------
// Kernel 2b: exact fp32 rescore of flagged rows (full 1024-code scan).
// 32 rows per CTA; aggregate-FLOP-bound, grid sized so all tiles resident.
// ---------------------------------------------------------------------------
__global__ __launch_bounds__(256)
void rescore_kernel(const float* __restrict__ x, const float* __restrict__ cb) {
    __shared__ float xs[RROWS][260];
    __shared__ int   rowid[RROWS];
    __shared__ float wv[8][8];
    __shared__ int   wi_[8][8];

    int tid  = threadIdx.x;
    int lane = tid & 31;
    int warp = tid >> 5;
    int tr   = tid >> 6;
    int tc   = tid & 63;
    int cnt  = g_flagcnt;

    const float4* x4  = reinterpret_cast<const float4*>(x);
    const float4* cb4 = reinterpret_cast<const float4*>(cb);

    for (int base = blockIdx.x * RROWS; base < cnt; base += gridDim.x * RROWS) {
        if (tid < RROWS)
            rowid[tid] = (base + tid < cnt) ? g_flagged[base + tid] : -1;
        __syncthreads();
        for (int i = tid; i < RROWS * 64; i += 256) {
            int r  = i >> 6;
            int c4 = i & 63;
            int row = rowid[r];
            if (row >= 0) {
                float4 v = x4[(size_t)row * 64 + c4];
                *reinterpret_cast<float4*>(&xs[r][c4 * 4]) = v;
            }
        }
        __syncthreads();

        float rb[8];
        int   ri_[8];
#pragma unroll
        for (int r = 0; r < 8; r++) { rb[r] = 3.4e38f; ri_[r] = 0; }

        for (int j = 0; j < 4; j++) {
            int c0 = j * 256 + tc * 4;
            float acc[8][4];
#pragma unroll
            for (int r = 0; r < 8; r++)
#pragma unroll
                for (int q = 0; q < 4; q++) acc[r][q] = 0.f;
#pragma unroll 4
            for (int d4 = 0; d4 < 64; d4++) {
                float4 e[4];
#pragma unroll
                for (int q = 0; q < 4; q++)
                    e[q] = cb4[(size_t)(c0 + q) * 64 + d4];
#pragma unroll
                for (int r = 0; r < 8; r++) {
                    float4 xv = *reinterpret_cast<const float4*>(
                        &xs[tr * 8 + r][d4 * 4]);
#pragma unroll
                    for (int q = 0; q < 4; q++)
                        acc[r][q] += xv.x * e[q].x + xv.y * e[q].y +
                                     xv.z * e[q].z + xv.w * e[q].w;
                }
            }
#pragma unroll
            for (int q = 0; q < 4; q++) {
                int code = c0 + q;
                float cn = g_cnorm[code];
#pragma unroll
                for (int r = 0; r < 8; r++) {
                    float s = cn - 2.f * acc[r][q];
                    if (s < rb[r] || (s == rb[r] && code < ri_[r])) {
                        rb[r] = s;
                        ri_[r] = code;
                    }
                }
            }
        }

        // warp lex-min reduce (all lanes same tr -> same rows)
#pragma unroll
        for (int r = 0; r < 8; r++) {
#pragma unroll
            for (int t = 1; t < 32; t <<= 1) {
                float os = __shfl_xor_sync(0xffffffffu, rb[r], t);
                int   oi = __shfl_xor_sync(0xffffffffu, ri_[r], t);
                if (os < rb[r] || (os == rb[r] && oi < ri_[r])) {
                    rb[r] = os;
                    ri_[r] = oi;
                }
            }
        }
        if (lane == 0)
#pragma unroll
            for (int r = 0; r < 8; r++) { wv[warp][r] = rb[r]; wi_[warp][r] = ri_[r]; }
        __syncthreads();
        if (tid < RROWS) {
            int trr = tid >> 3, l8 = tid & 7;
            float a = wv[2 * trr][l8];
            int   ai = wi_[2 * trr][l8];
            float b = wv[2 * trr + 1][l8];
            int   bi = wi_[2 * trr + 1][l8];
            if (b < a || (b == a && bi < ai)) { a = b; ai = bi; }
            int row = rowid[tid];
            if (row >= 0) g_argmin[row] = ai;
        }
        __syncthreads();
    }
}

// ---------------------------------------------------------------------------
// Kernel 3: gather quantized = codebook[argmin], accumulate sum((q-x)^2)
// ---------------------------------------------------------------------------
__global__ __launch_bounds__(256)
void gather_kernel(const float* __restrict__ x, const float* __restrict__ cb,
                   float* __restrict__ out, int nrows) {
    __shared__ float warp_s[8];
    int lane = threadIdx.x & 31;
    int wip  = threadIdx.x >> 5;
    int row  = blockIdx.x * 8 + wip;

    float s = 0.f;
    if (row < nrows) {
        int idx = g_argmin[row];
        const float4* q4 = reinterpret_cast<const float4*>(cb + (size_t)idx * D);
        const float4* xr = reinterpret_cast<const float4*>(x + (size_t)row * D);
        float4* o4 = reinterpret_cast<float4*>(out) + (size_t)row * (D / 4);
#pragma unroll
        for (int t = 0; t < 2; t++) {
            int p = lane + 32 * t;
            float4 q  = q4[p];
            float4 xv = xr[p];
            o4[p] = q;
            float dx = q.x - xv.x, dy = q.y - xv.y;
            float dz = q.z - xv.z, dw = q.w - xv.w;
            s += dx * dx + dy * dy + dz * dz + dw * dw;
        }
    }
#pragma unroll
    for (int off = 16; off > 0; off >>= 1)
        s += __shfl_xor_sync(0xffffffffu, s, off);
    if (lane == 0) warp_s[wip] = s;
    __syncthreads();
    if (threadIdx.x == 0) {
        double tot = 0.0;
#pragma unroll
        for (int w = 0; w < 8; w++) tot += (double)warp_s[w];
        g_partial[blockIdx.x] = tot;
    }
}

// ---------------------------------------------------------------------------
// Kernel 4: final loss reduction (deterministic)
// ---------------------------------------------------------------------------
__global__ void loss_kernel(float* __restrict__ loss_out, int nblocks,
                            float inv_nd) {
    __shared__ double sh[256];
    double s = 0.0;
    for (int i = threadIdx.x; i < nblocks; i += 256) s += g_partial[i];
    sh[threadIdx.x] = s;
    __syncthreads();
    for (int off = 128; off > 0; off >>= 1) {
        if (threadIdx.x < off) sh[threadIdx.x] += sh[threadIdx.x + off];
        __syncthreads();
    }
    if (threadIdx.x == 0)
        *loss_out = (float)(1.25 * sh[0] * (double)inv_nd);
}

// ---------------------------------------------------------------------------
extern "C" void kernel_launch(void* const* d_in, const int* in_sizes, int n_in,
                              void* d_out, int out_size) {
    const float* x  = (const float*)d_in[0];
    const float* cb = (const float*)d_in[1];
    float* out = (float*)d_out;

    int n     = in_sizes[0];       // 16777216
    int nrows = n / D;             // 65536

    cudaFuncSetAttribute(argmin_kernel,
                         cudaFuncAttributeMaxDynamicSharedMemorySize,
                         SMEM_BYTES);

    norms_kernel<<<NCODES, 32>>>(cb);
    argmin_kernel<<<nrows / BM, 256, SMEM_BYTES>>>(x, cb);
    rescore_kernel<<<592, 256>>>(x, cb);

    int gblocks = (nrows + 7) / 8;      // 8192
    gather_kernel<<<gblocks, 256>>>(x, cb, out, nrows);
    loss_kernel<<<1, 256>>>(out + (out_size - 1), gblocks, 1.0f / (float)n);
}